// round 1
// baseline (speedup 1.0000x reference)
#include <cuda_runtime.h>

// UWNeRF RGB renderer: R rays x S=128 samples.
// Warp-per-ray, 4 consecutive samples per lane. Exclusive cumsums done as
// lane-local prefix + one 5-step warp scan of lane totals per quantity
// (7 scans/ray total). All global loads coalesced (float4).

#define FULL 0xffffffffu
static constexpr int S = 128;

__device__ __forceinline__ float excl_scan32(float x, int lane) {
    float incl = x;
#pragma unroll
    for (int d = 1; d < 32; d <<= 1) {
        float v = __shfl_up_sync(FULL, incl, d);
        if (lane >= d) incl += v;
    }
    return incl - x;
}

__device__ __forceinline__ float wred(float v) {
#pragma unroll
    for (int m = 16; m; m >>= 1) v += __shfl_xor_sync(FULL, v, m);
    return v;
}

__global__ void __launch_bounds__(256)
uwnerf_kernel(const float* __restrict__ densities,
              const float* __restrict__ rgbs,
              const float* __restrict__ veil,
              const float* __restrict__ dirc,
              const float* __restrict__ backc,
              const float* __restrict__ deltas,
              float* __restrict__ out, int R)
{
    const int warp = blockIdx.x * (blockDim.x >> 5) + (threadIdx.x >> 5);
    const int lane = threadIdx.x & 31;
    if (warp >= R) return;
    const int r = warp;
    const int s0 = lane * 4;          // this lane's first sample
    const long base1 = (long)r * S + s0;      // 1-channel arrays
    const long base3 = base1 * 3;             // 3-channel arrays

    // ---- deltas & densities (float4, fully coalesced) ----
    const float4 del4 = *reinterpret_cast<const float4*>(deltas + base1);
    const float4 den4 = *reinterpret_cast<const float4*>(densities + base1);
    float del[4] = {del4.x, del4.y, del4.z, del4.w};
    float dd[4]  = {del4.x * den4.x, del4.y * den4.y, del4.z * den4.z, del4.w * den4.w};

    // object transmittance: exclusive cumsum of dd
    float totO = dd[0] + dd[1] + dd[2] + dd[3];
    float cum = excl_scan32(totO, lane);
    float w[4], wsum = 0.f;
#pragma unroll
    for (int j = 0; j < 4; j++) {
        float T = __expf(-cum);
        float alpha = 1.f - __expf(-dd[j]);
        w[j] = alpha * T;
        wsum += w[j];
        cum += dd[j];
    }

    // ---- rgbs (3 x float4 per lane = 12 consecutive floats) ----
    float rgb[12];
    {
        const float4* p = reinterpret_cast<const float4*>(rgbs + base3);
        float4 a = p[0], b = p[1], c = p[2];
        rgb[0]=a.x; rgb[1]=a.y; rgb[2]=a.z; rgb[3]=a.w;
        rgb[4]=b.x; rgb[5]=b.y; rgb[6]=b.z; rgb[7]=b.w;
        rgb[8]=c.x; rgb[9]=c.y; rgb[10]=c.z; rgb[11]=c.w;
    }

    float rest[3] = {0.f, 0.f, 0.f};
#pragma unroll
    for (int j = 0; j < 4; j++) {
#pragma unroll
        for (int c = 0; c < 3; c++) rest[c] += w[j] * rgb[j * 3 + c];
    }

    // ---- direct attenuation (per channel: exclusive cumsum of delta*dc) ----
    float dcv[12];
    {
        const float4* p = reinterpret_cast<const float4*>(dirc + base3);
        float4 a = p[0], b = p[1], c = p[2];
        dcv[0]=a.x; dcv[1]=a.y; dcv[2]=a.z; dcv[3]=a.w;
        dcv[4]=b.x; dcv[5]=b.y; dcv[6]=b.z; dcv[7]=b.w;
        dcv[8]=c.x; dcv[9]=c.y; dcv[10]=c.z; dcv[11]=c.w;
    }
    float dirr[3];
#pragma unroll
    for (int c = 0; c < 3; c++) {
        float x[4];
#pragma unroll
        for (int j = 0; j < 4; j++) x[j] = del[j] * dcv[j * 3 + c];
        float tot = x[0] + x[1] + x[2] + x[3];
        float cc = excl_scan32(tot, lane);
        float acc = 0.f;
#pragma unroll
        for (int j = 0; j < 4; j++) {
            float atten = __expf(-cc);
            acc += w[j] * atten * rgb[j * 3 + c];
            cc += x[j];
        }
        dirr[c] = acc;
    }

    // ---- backscatter (per channel: 1 - exp(-excl cumsum of delta*bc)) ----
    float bcv[12], vl[12];
    {
        const float4* p = reinterpret_cast<const float4*>(backc + base3);
        float4 a = p[0], b = p[1], c = p[2];
        bcv[0]=a.x; bcv[1]=a.y; bcv[2]=a.z; bcv[3]=a.w;
        bcv[4]=b.x; bcv[5]=b.y; bcv[6]=b.z; bcv[7]=b.w;
        bcv[8]=c.x; bcv[9]=c.y; bcv[10]=c.z; bcv[11]=c.w;
    }
    {
        const float4* p = reinterpret_cast<const float4*>(veil + base3);
        float4 a = p[0], b = p[1], c = p[2];
        vl[0]=a.x; vl[1]=a.y; vl[2]=a.z; vl[3]=a.w;
        vl[4]=b.x; vl[5]=b.y; vl[6]=b.z; vl[7]=b.w;
        vl[8]=c.x; vl[9]=c.y; vl[10]=c.z; vl[11]=c.w;
    }
    float ob[3];
#pragma unroll
    for (int c = 0; c < 3; c++) {
        float x[4];
#pragma unroll
        for (int j = 0; j < 4; j++) x[j] = del[j] * bcv[j * 3 + c];
        float tot = x[0] + x[1] + x[2] + x[3];
        float cc = excl_scan32(tot, lane);
        float acc = 0.f;
#pragma unroll
        for (int j = 0; j < 4; j++) {
            float batt = 1.f - __expf(-cc);
            acc += w[j] * batt * vl[j * 3 + c];
            cc += x[j];
        }
        ob[c] = acc;
    }

    // ---- warp reductions (results valid in all lanes; lane 0 writes) ----
    wsum = wred(wsum);
#pragma unroll
    for (int c = 0; c < 3; c++) { rest[c] = wred(rest[c]); dirr[c] = wred(dirr[c]); ob[c] = wred(ob[c]); }

    if (lane == 0) {
        float mask = __saturatef(wsum);
        // lane 0 holds veil at sample 0 of this ray in vl[0..2]
#pragma unroll
        for (int c = 0; c < 3; c++) {
            float back_ray = ob[c] + (1.f - mask) * vl[c];
            out[0L * R * 3 + r * 3 + c] = __saturatef(dirr[c] + back_ray);  // rgb
            out[1L * R * 3 + r * 3 + c] = __saturatef(rest[c]);             // restored
            out[2L * R * 3 + r * 3 + c] = __saturatef(dirr[c]);             // direct
            out[3L * R * 3 + r * 3 + c] = __saturatef(back_ray);            // backscatter
        }
    }
}

extern "C" void kernel_launch(void* const* d_in, const int* in_sizes, int n_in,
                              void* d_out, int out_size) {
    const float* densities = (const float*)d_in[0];
    const float* rgbs      = (const float*)d_in[1];
    const float* veil      = (const float*)d_in[2];
    const float* dirc      = (const float*)d_in[3];
    const float* backc     = (const float*)d_in[4];
    const float* deltas    = (const float*)d_in[5];
    float* out = (float*)d_out;

    int R = in_sizes[0] / S;           // densities has R*S*1 elements
    const int warps_per_block = 256 / 32;
    int blocks = (R + warps_per_block - 1) / warps_per_block;
    uwnerf_kernel<<<blocks, 256>>>(densities, rgbs, veil, dirc, backc, deltas, out, R);
}

// round 8
// speedup vs baseline: 1.0271x; 1.0271x over previous
#include <cuda_runtime.h>

// UWNeRF RGB renderer: R rays x S=128 samples, warp-per-ray, 4 samples/lane.
// R2 hypothesis (7th submission; 6x broker timeout): all 14 float4 global
// loads hoisted to the top of the kernel so the full 224B/lane is in flight
// before the first dependent warp scan (maximize MLP -> DRAM utilization).

#define FULL 0xffffffffu
static constexpr int S = 128;

__device__ __forceinline__ float excl_scan32(float x, int lane) {
    float incl = x;
#pragma unroll
    for (int d = 1; d < 32; d <<= 1) {
        float v = __shfl_up_sync(FULL, incl, d);
        if (lane >= d) incl += v;
    }
    return incl - x;
}

__device__ __forceinline__ float wred(float v) {
#pragma unroll
    for (int m = 16; m; m >>= 1) v += __shfl_xor_sync(FULL, v, m);
    return v;
}

__global__ void __launch_bounds__(256)
uwnerf_kernel(const float* __restrict__ densities,
              const float* __restrict__ rgbs,
              const float* __restrict__ veil,
              const float* __restrict__ dirc,
              const float* __restrict__ backc,
              const float* __restrict__ deltas,
              float* __restrict__ out, int R)
{
    const int warp = blockIdx.x * (blockDim.x >> 5) + (threadIdx.x >> 5);
    const int lane = threadIdx.x & 31;
    if (warp >= R) return;
    const int r = warp;
    const int s0 = lane * 4;
    const long base1 = (long)r * S + s0;
    const long base3 = base1 * 3;

    // ================= ALL GLOBAL LOADS FIRST (14 x LDG.128) =================
    const float4 del4 = *reinterpret_cast<const float4*>(deltas + base1);
    const float4 den4 = *reinterpret_cast<const float4*>(densities + base1);
    const float4* rp = reinterpret_cast<const float4*>(rgbs + base3);
    const float4 rg0 = rp[0], rg1 = rp[1], rg2 = rp[2];
    const float4* dp = reinterpret_cast<const float4*>(dirc + base3);
    const float4 dc0 = dp[0], dc1 = dp[1], dc2 = dp[2];
    const float4* bp = reinterpret_cast<const float4*>(backc + base3);
    const float4 bc0 = bp[0], bc1 = bp[1], bc2 = bp[2];
    const float4* vp = reinterpret_cast<const float4*>(veil + base3);
    const float4 vl0 = vp[0], vl1 = vp[1], vl2 = vp[2];
    // ========================================================================

    float del[4] = {del4.x, del4.y, del4.z, del4.w};
    float dd[4]  = {del4.x * den4.x, del4.y * den4.y, del4.z * den4.z, del4.w * den4.w};

    // object transmittance weights
    float totO = dd[0] + dd[1] + dd[2] + dd[3];
    float cum = excl_scan32(totO, lane);
    float w[4], wsum = 0.f;
#pragma unroll
    for (int j = 0; j < 4; j++) {
        float T = __expf(-cum);
        float alpha = 1.f - __expf(-dd[j]);
        w[j] = alpha * T;
        wsum += w[j];
        cum += dd[j];
    }

    float rgb[12] = {rg0.x, rg0.y, rg0.z, rg0.w, rg1.x, rg1.y, rg1.z, rg1.w,
                     rg2.x, rg2.y, rg2.z, rg2.w};
    float dcv[12] = {dc0.x, dc0.y, dc0.z, dc0.w, dc1.x, dc1.y, dc1.z, dc1.w,
                     dc2.x, dc2.y, dc2.z, dc2.w};
    float bcv[12] = {bc0.x, bc0.y, bc0.z, bc0.w, bc1.x, bc1.y, bc1.z, bc1.w,
                     bc2.x, bc2.y, bc2.z, bc2.w};
    float vl[12]  = {vl0.x, vl0.y, vl0.z, vl0.w, vl1.x, vl1.y, vl1.z, vl1.w,
                     vl2.x, vl2.y, vl2.z, vl2.w};

    float rest[3] = {0.f, 0.f, 0.f};
#pragma unroll
    for (int j = 0; j < 4; j++)
#pragma unroll
        for (int c = 0; c < 3; c++) rest[c] += w[j] * rgb[j * 3 + c];

    // direct attenuation
    float dirr[3];
#pragma unroll
    for (int c = 0; c < 3; c++) {
        float x[4];
#pragma unroll
        for (int j = 0; j < 4; j++) x[j] = del[j] * dcv[j * 3 + c];
        float tot = x[0] + x[1] + x[2] + x[3];
        float cc = excl_scan32(tot, lane);
        float acc = 0.f;
#pragma unroll
        for (int j = 0; j < 4; j++) {
            acc += w[j] * __expf(-cc) * rgb[j * 3 + c];
            cc += x[j];
        }
        dirr[c] = acc;
    }

    // backscatter
    float ob[3];
#pragma unroll
    for (int c = 0; c < 3; c++) {
        float x[4];
#pragma unroll
        for (int j = 0; j < 4; j++) x[j] = del[j] * bcv[j * 3 + c];
        float tot = x[0] + x[1] + x[2] + x[3];
        float cc = excl_scan32(tot, lane);
        float acc = 0.f;
#pragma unroll
        for (int j = 0; j < 4; j++) {
            acc += w[j] * (1.f - __expf(-cc)) * vl[j * 3 + c];
            cc += x[j];
        }
        ob[c] = acc;
    }

    // warp reductions, lane 0 writes
    wsum = wred(wsum);
#pragma unroll
    for (int c = 0; c < 3; c++) { rest[c] = wred(rest[c]); dirr[c] = wred(dirr[c]); ob[c] = wred(ob[c]); }

    if (lane == 0) {
        float mask = __saturatef(wsum);
#pragma unroll
        for (int c = 0; c < 3; c++) {
            float back_ray = ob[c] + (1.f - mask) * vl[c];  // vl[0..2] = veil @ sample 0
            out[0L * R * 3 + r * 3 + c] = __saturatef(dirr[c] + back_ray);  // rgb
            out[1L * R * 3 + r * 3 + c] = __saturatef(rest[c]);             // restored
            out[2L * R * 3 + r * 3 + c] = __saturatef(dirr[c]);             // direct
            out[3L * R * 3 + r * 3 + c] = __saturatef(back_ray);            // backscatter
        }
    }
}

extern "C" void kernel_launch(void* const* d_in, const int* in_sizes, int n_in,
                              void* d_out, int out_size) {
    const float* densities = (const float*)d_in[0];
    const float* rgbs      = (const float*)d_in[1];
    const float* veil      = (const float*)d_in[2];
    const float* dirc      = (const float*)d_in[3];
    const float* backc     = (const float*)d_in[4];
    const float* deltas    = (const float*)d_in[5];
    float* out = (float*)d_out;

    int R = in_sizes[0] / S;
    const int warps_per_block = 256 / 32;
    int blocks = (R + warps_per_block - 1) / warps_per_block;
    uwnerf_kernel<<<blocks, 256>>>(densities, rgbs, veil, dirc, backc, deltas, out, R);
}